// round 1
// baseline (speedup 1.0000x reference)
#include <cuda_runtime.h>
#include <math.h>

// Problem constants
#define Bb   4
#define Ss   1024
#define Ee   1024
#define Hh   16
#define HDs  64
#define MTOT 4096      // B*S
#define E3   3072      // 3*E

// Scratch (device globals — no cudaMalloc allowed)
__device__ float g_qkv[MTOT * E3];    // [B*S, 3E]
__device__ float g_attn[MTOT * Ee];   // [B*S, E]

// ------------------------- SGEMM + bias -------------------------
// C[M,N] = A[M,K] @ W[K,N] + bias[N]; M%128==0, N%128==0, K%16==0
#define BM 128
#define BN 128
#define BK 16
#define TM 8
#define TN 8

__global__ __launch_bounds__(256)
void sgemm_bias(const float* __restrict__ A,
                const float* __restrict__ W,
                const float* __restrict__ bias,
                float* __restrict__ C,
                int M, int N, int K)
{
    __shared__ float As[BK][BM + 4];   // +4 floats keeps 16B alignment (132*4=528=33*16)
    __shared__ float Bs[BK][BN];

    const int tid = threadIdx.x;
    const int tx  = tid & 15;
    const int ty  = tid >> 4;
    const int bm  = blockIdx.y * BM;
    const int bn  = blockIdx.x * BN;

    float acc[TM][TN];
#pragma unroll
    for (int i = 0; i < TM; i++)
#pragma unroll
        for (int j = 0; j < TN; j++) acc[i][j] = 0.0f;

    for (int ko = 0; ko < K; ko += BK) {
        // Load A tile (BMxBK) transposed into As[k][m]
#pragma unroll
        for (int it = 0; it < 2; it++) {
            int idx  = tid * 2 + it;      // 0..511 float4s
            int row  = idx >> 2;          // 0..127
            int quad = idx & 3;           // 0..3 (k quad)
            float4 v = *(const float4*)&A[(size_t)(bm + row) * K + ko + quad * 4];
            As[quad * 4 + 0][row] = v.x;
            As[quad * 4 + 1][row] = v.y;
            As[quad * 4 + 2][row] = v.z;
            As[quad * 4 + 3][row] = v.w;
        }
        // Load B tile (BKxBN) natural
#pragma unroll
        for (int it = 0; it < 2; it++) {
            int idx = tid * 2 + it;       // 0..511
            int row = idx >> 5;           // 0..15
            int q   = idx & 31;           // 0..31
            *(float4*)&Bs[row][q * 4] =
                *(const float4*)&W[(size_t)(ko + row) * N + bn + q * 4];
        }
        __syncthreads();

#pragma unroll
        for (int k = 0; k < BK; k++) {
            float a[TM], b[TN];
#pragma unroll
            for (int i = 0; i < TM; i++) a[i] = As[k][ty * TM + i];
#pragma unroll
            for (int j = 0; j < TN; j++) b[j] = Bs[k][tx * TN + j];
#pragma unroll
            for (int i = 0; i < TM; i++)
#pragma unroll
                for (int j = 0; j < TN; j++) acc[i][j] += a[i] * b[j];
        }
        __syncthreads();
    }

    // Epilogue with bias
#pragma unroll
    for (int i = 0; i < TM; i++) {
        int gr = bm + ty * TM + i;
#pragma unroll
        for (int j4 = 0; j4 < TN; j4 += 4) {
            int gc = bn + tx * TN + j4;
            float4 o;
            o.x = acc[i][j4 + 0] + bias[gc + 0];
            o.y = acc[i][j4 + 1] + bias[gc + 1];
            o.z = acc[i][j4 + 2] + bias[gc + 2];
            o.w = acc[i][j4 + 3] + bias[gc + 3];
            *(float4*)&C[(size_t)gr * N + gc] = o;
        }
    }
}

// ------------------------- Flash-style causal attention -------------------------
// grid: (S/64, B*H); block: 256 = 16x16 threads, each owns 4 rows x 4 cols
#define QT   64
#define KT   64
#define PADW 68   // 68 floats = 272B = 17*16 -> float4-aligned rows

__global__ __launch_bounds__(256)
void attn_kernel(const int* __restrict__ mask, float* __restrict__ out)
{
    extern __shared__ float sm[];
    float* Qs = sm;                  // [d][r]  64 x PADW
    float* Ks = Qs + 64 * PADW;      // [d][c]
    float* Vs = Ks + 64 * PADW;      // [kv_row][d]
    float* Ps = Vs + 64 * PADW;      // [kv_col][q_row]

    const int tid = threadIdx.x;
    const int tx  = tid & 15;
    const int ty  = tid >> 4;
    const int qtile = blockIdx.x;
    const int bh    = blockIdx.y;
    const int b     = bh >> 4;       // /H
    const int h     = bh & 15;

    const int r0 = ty * 4;           // local q rows
    const int c0 = tx * 4;           // local kv cols / hd cols
    const float scale = 0.125f;      // 1/sqrt(64)

    const int qrow0 = qtile * QT;

    // Load Q tile transposed: Qs[d][r]
    for (int i = tid; i < 64 * 16; i += 256) {
        int row  = i >> 4;
        int quad = i & 15;
        const float* src = &g_qkv[(size_t)(b * Ss + qrow0 + row) * E3 + h * HDs + quad * 4];
        float4 v = *(const float4*)src;
        Qs[(quad * 4 + 0) * PADW + row] = v.x;
        Qs[(quad * 4 + 1) * PADW + row] = v.y;
        Qs[(quad * 4 + 2) * PADW + row] = v.z;
        Qs[(quad * 4 + 3) * PADW + row] = v.w;
    }

    float m_i[4], l_i[4], o[4][4];
#pragma unroll
    for (int r = 0; r < 4; r++) {
        m_i[r] = -1e30f; l_i[r] = 0.0f;
#pragma unroll
        for (int c = 0; c < 4; c++) o[r][c] = 0.0f;
    }
    int g_r[4];
#pragma unroll
    for (int r = 0; r < 4; r++) g_r[r] = qrow0 + r0 + r;

    for (int j = 0; j <= qtile; j++) {
        __syncthreads();   // protect Ks/Vs/Ps from previous iteration readers
        const int krow0 = j * KT;

        // Load K transposed + V natural
        for (int i = tid; i < 64 * 16; i += 256) {
            int row  = i >> 4;
            int quad = i & 15;
            const float* kp = &g_qkv[(size_t)(b * Ss + krow0 + row) * E3 + Ee + h * HDs + quad * 4];
            float4 kv = *(const float4*)kp;
            Ks[(quad * 4 + 0) * PADW + row] = kv.x;
            Ks[(quad * 4 + 1) * PADW + row] = kv.y;
            Ks[(quad * 4 + 2) * PADW + row] = kv.z;
            Ks[(quad * 4 + 3) * PADW + row] = kv.w;
            float4 vv = *(const float4*)(kp + Ee);  // V section is +E after K
            *(float4*)&Vs[row * PADW + quad * 4] = vv;
        }
        __syncthreads();

        // S = Q K^T
        float s[4][4];
#pragma unroll
        for (int r = 0; r < 4; r++)
#pragma unroll
            for (int c = 0; c < 4; c++) s[r][c] = 0.0f;

        for (int d = 0; d < 64; d++) {
            float4 q4 = *(const float4*)&Qs[d * PADW + r0];
            float4 k4 = *(const float4*)&Ks[d * PADW + c0];
            float qa[4] = {q4.x, q4.y, q4.z, q4.w};
            float ka[4] = {k4.x, k4.y, k4.z, k4.w};
#pragma unroll
            for (int r = 0; r < 4; r++)
#pragma unroll
                for (int c = 0; c < 4; c++) s[r][c] += qa[r] * ka[c];
        }

        // scale + causal + key mask
        float kvalid[4];
#pragma unroll
        for (int c = 0; c < 4; c++) {
            int gc = krow0 + c0 + c;
            kvalid[c] = (mask[b * Ss + gc] != 0) ? 1.0f : 0.0f;
        }
#pragma unroll
        for (int r = 0; r < 4; r++)
#pragma unroll
            for (int c = 0; c < 4; c++) {
                int gc = krow0 + c0 + c;
                bool ok = (gc <= g_r[r]) && (kvalid[c] > 0.5f);
                s[r][c] = ok ? s[r][c] * scale : -1e30f;
            }

        // online softmax
        float mloc[4];
#pragma unroll
        for (int r = 0; r < 4; r++) {
            mloc[r] = fmaxf(fmaxf(s[r][0], s[r][1]), fmaxf(s[r][2], s[r][3]));
#pragma unroll
            for (int off = 8; off >= 1; off >>= 1)
                mloc[r] = fmaxf(mloc[r], __shfl_xor_sync(0xffffffffu, mloc[r], off));
        }

        float alpha[4];
#pragma unroll
        for (int r = 0; r < 4; r++) {
            float mn = fmaxf(m_i[r], mloc[r]);
            alpha[r] = __expf(m_i[r] - mn);
            m_i[r]   = mn;
        }

        float rowsum[4];
#pragma unroll
        for (int r = 0; r < 4; r++) {
            float rs = 0.0f;
#pragma unroll
            for (int c = 0; c < 4; c++) {
                float p = __expf(s[r][c] - m_i[r]);
                s[r][c] = p;
                rs += p;
            }
#pragma unroll
            for (int off = 8; off >= 1; off >>= 1)
                rs += __shfl_xor_sync(0xffffffffu, rs, off);
            rowsum[r] = rs;
        }

#pragma unroll
        for (int r = 0; r < 4; r++) {
            l_i[r] = l_i[r] * alpha[r] + rowsum[r];
#pragma unroll
            for (int c = 0; c < 4; c++) o[r][c] *= alpha[r];
        }

        // store P transposed: Ps[kv_col][q_row]
#pragma unroll
        for (int r = 0; r < 4; r++)
#pragma unroll
            for (int c = 0; c < 4; c++)
                Ps[(c0 + c) * PADW + (r0 + r)] = s[r][c];
        __syncthreads();

        // O += P @ V
        for (int k = 0; k < 64; k++) {
            float4 p4 = *(const float4*)&Ps[k * PADW + r0];
            float4 v4 = *(const float4*)&Vs[k * PADW + c0];
            float pa[4] = {p4.x, p4.y, p4.z, p4.w};
            float va[4] = {v4.x, v4.y, v4.z, v4.w};
#pragma unroll
            for (int r = 0; r < 4; r++)
#pragma unroll
                for (int c = 0; c < 4; c++) o[r][c] += pa[r] * va[c];
        }
    }

    // normalize + write [b, s, E] with head h at cols h*64
#pragma unroll
    for (int r = 0; r < 4; r++) {
        float inv = 1.0f / l_i[r];
#pragma unroll
        for (int c = 0; c < 4; c++) {
            out[(size_t)(b * Ss + g_r[r]) * Ee + h * HDs + c0 + c] = o[r][c] * inv;
        }
    }
}

// ------------------------- launch -------------------------
extern "C" void kernel_launch(void* const* d_in, const int* in_sizes, int n_in,
                              void* d_out, int out_size)
{
    const float* X     = (const float*)d_in[0];   // hidden_states [B,S,E]
    const int*   mask  = (const int*)  d_in[1];   // attention_mask [B,S]
    const float* Wqkv  = (const float*)d_in[2];   // [E, 3E]
    const float* bqkv  = (const float*)d_in[3];   // [3E]
    const float* Wproj = (const float*)d_in[4];   // [E, E]
    const float* bproj = (const float*)d_in[5];   // [E]
    float* out = (float*)d_out;                   // [B,S,E] fp32

    float* qkv;  cudaGetSymbolAddress((void**)&qkv,  g_qkv);
    float* attn; cudaGetSymbolAddress((void**)&attn, g_attn);

    // 1) QKV = X @ Wqkv + bqkv
    {
        dim3 grid(E3 / BN, MTOT / BM);
        sgemm_bias<<<grid, 256>>>(X, Wqkv, bqkv, qkv, MTOT, E3, Ee);
    }

    // 2) causal attention
    {
        const int smem = 4 * 64 * PADW * (int)sizeof(float);  // 69632 B
        cudaFuncSetAttribute(attn_kernel, cudaFuncAttributeMaxDynamicSharedMemorySize, smem);
        dim3 grid(Ss / QT, Bb * Hh);
        attn_kernel<<<grid, 256, smem>>>(mask, attn);
    }

    // 3) out = attn @ Wproj + bproj
    {
        dim3 grid(Ee / BN, MTOT / BM);
        sgemm_bias<<<grid, 256>>>(attn, Wproj, bproj, out, MTOT, Ee, Ee);
    }
}

// round 3
// speedup vs baseline: 1.6586x; 1.6586x over previous
#include <cuda_runtime.h>
#include <cuda_bf16.h>
#include <cstdint>
#include <math.h>

// ---------------- problem constants ----------------
#define Bb   4
#define Ss   1024
#define Ee   1024
#define Hh   16
#define HDs  64
#define MTOT 4096      // B*S
#define E3   3072      // 3*E
#define Kdim 1024

// ---------------- scratch (device globals) ----------------
__device__ float          g_qkv [MTOT * E3];     // [B*S, 3E] fp32
__device__ float          g_attn[MTOT * Ee];     // [B*S, E]  fp32
__device__ __nv_bfloat16  g_xhi [MTOT * Ee];
__device__ __nv_bfloat16  g_xlo [MTOT * Ee];
__device__ __nv_bfloat16  g_wqh [E3 * Ee];       // Wqkv^T [3E][E]
__device__ __nv_bfloat16  g_wql [E3 * Ee];
__device__ __nv_bfloat16  g_wph [Ee * Ee];       // Wproj^T
__device__ __nv_bfloat16  g_wpl [Ee * Ee];
__device__ __nv_bfloat16  g_ahi [MTOT * Ee];
__device__ __nv_bfloat16  g_alo [MTOT * Ee];

// ---------------- split fp32 -> (bf16 hi, bf16 lo) ----------------
__global__ __launch_bounds__(256)
void split_hi_lo(const float* __restrict__ x,
                 __nv_bfloat16* __restrict__ hi,
                 __nv_bfloat16* __restrict__ lo, int n)
{
    int i = (blockIdx.x * 256 + threadIdx.x) * 4;
    if (i >= n) return;
    float4 v = *(const float4*)(x + i);
    __nv_bfloat16 h[4], l[4];
    float vv[4] = {v.x, v.y, v.z, v.w};
#pragma unroll
    for (int q = 0; q < 4; q++) {
        h[q] = __float2bfloat16_rn(vv[q]);
        l[q] = __float2bfloat16_rn(vv[q] - __bfloat162float(h[q]));
    }
    *(uint2*)(hi + i) = *(uint2*)h;
    *(uint2*)(lo + i) = *(uint2*)l;
}

// ---------------- transpose + split: W[K][N] -> T_hi/lo[N][K] ----------------
__global__ __launch_bounds__(256)
void transpose_split(const float* __restrict__ W,
                     __nv_bfloat16* __restrict__ Thi,
                     __nv_bfloat16* __restrict__ Tlo, int K, int N)
{
    __shared__ float tile[32][33];
    int n0 = blockIdx.x * 32, k0 = blockIdx.y * 32;
    int tx = threadIdx.x, ty = threadIdx.y;   // 32 x 8
#pragma unroll
    for (int i = 0; i < 32; i += 8)
        tile[ty + i][tx] = W[(size_t)(k0 + ty + i) * N + n0 + tx];
    __syncthreads();
#pragma unroll
    for (int i = 0; i < 32; i += 8) {
        int n = n0 + ty + i, k = k0 + tx;
        float v = tile[tx][ty + i];
        __nv_bfloat16 h = __float2bfloat16_rn(v);
        Thi[(size_t)n * K + k] = h;
        Tlo[(size_t)n * K + k] = __float2bfloat16_rn(v - __bfloat162float(h));
    }
}

// ---------------- mma.sync helpers ----------------
__device__ __forceinline__ void mma16816(float* c, const uint32_t* a, const uint32_t* b)
{
    asm volatile(
        "mma.sync.aligned.m16n8k16.row.col.f32.bf16.bf16.f32 "
        "{%0,%1,%2,%3}, {%4,%5,%6,%7}, {%8,%9}, {%0,%1,%2,%3};"
        : "+f"(c[0]), "+f"(c[1]), "+f"(c[2]), "+f"(c[3])
        : "r"(a[0]), "r"(a[1]), "r"(a[2]), "r"(a[3]), "r"(b[0]), "r"(b[1]));
}
__device__ __forceinline__ void cp16(uint32_t saddr, const void* g)
{
    asm volatile("cp.async.cg.shared.global [%0], [%1], 16;"
                 :: "r"(saddr), "l"(g));
}
__device__ __forceinline__ uint32_t smem_u32(const void* p) {
    uint32_t a;
    asm("{ .reg .u64 t; cvta.to.shared.u64 t, %1; cvt.u32.u64 %0, t; }"
        : "=r"(a) : "l"(p));
    return a;
}

// ---------------- split-bf16 tensor-core GEMM (mma.sync) ----------------
// C[m][n] = sum_k A[m][k]*Wt[n][k] + bias[n]
// block tile 128x128, BK=32, 8 warps (2x4), warp tile 64x32, 2-stage cp.async.
#define GBK      32
#define GSTRIDE  40                        // bf16 elems per smem row (pad 8)
#define ARR_B    (128 * GSTRIDE * 2)       // 10240 bytes per array
#define STAGE_B  (4 * ARR_B)               // Ah, Al, Bh, Bl
#define GEMM_SMEM (2 * STAGE_B)            // 81920

__global__ __launch_bounds__(256, 1)
void gemm_mma(const __nv_bfloat16* __restrict__ Ahi, const __nv_bfloat16* __restrict__ Alo,
              const __nv_bfloat16* __restrict__ Bhi, const __nv_bfloat16* __restrict__ Blo,
              const float* __restrict__ bias, float* __restrict__ C, int N)
{
    extern __shared__ char smem[];
    const uint32_t sb = smem_u32(smem);
    const int tid  = threadIdx.x;
    const int wid  = tid >> 5, lane = tid & 31;
    const int wm   = wid >> 2, wn = wid & 3;          // warp grid 2 x 4
    const int g    = lane >> 2, tig = lane & 3;
    const int bm   = blockIdx.y * 128, bn = blockIdx.x * 128;
    const int NC   = Kdim / GBK;                      // 32 chunks

    float acc[4][4][4];
#pragma unroll
    for (int im = 0; im < 4; im++)
#pragma unroll
        for (int in = 0; in < 4; in++)
#pragma unroll
            for (int q = 0; q < 4; q++) acc[im][in][q] = 0.0f;

    // prefetch lambda-equivalent
    auto prefetch = [&](int c, int st) {
#pragma unroll
        for (int i = 0; i < 8; i++) {
            int idx = tid + i * 256;        // 0..2047
            int arr = idx >> 9;             // 0:Ah 1:Al 2:Bh 3:Bl
            int e   = idx & 511;
            int row = e >> 2;               // 0..127
            int seg = e & 3;                // 16B segment along k
            const __nv_bfloat16* gp;
            size_t koff = (size_t)c * GBK + seg * 8;
            if      (arr == 0) gp = Ahi + (size_t)(bm + row) * Kdim + koff;
            else if (arr == 1) gp = Alo + (size_t)(bm + row) * Kdim + koff;
            else if (arr == 2) gp = Bhi + (size_t)(bn + row) * Kdim + koff;
            else               gp = Blo + (size_t)(bn + row) * Kdim + koff;
            uint32_t sa = sb + st * STAGE_B + arr * ARR_B + (row * GSTRIDE + seg * 8) * 2;
            cp16(sa, gp);
        }
        asm volatile("cp.async.commit_group;");
    };

    prefetch(0, 0);

    for (int c = 0; c < NC; c++) {
        const int st = c & 1;
        if (c + 1 < NC) {
            prefetch(c + 1, (c + 1) & 1);
            asm volatile("cp.async.wait_group 1;");
        } else {
            asm volatile("cp.async.wait_group 0;");
        }
        __syncthreads();

        const __nv_bfloat16* sAh = (const __nv_bfloat16*)(smem + st * STAGE_B);
        const __nv_bfloat16* sAl = (const __nv_bfloat16*)(smem + st * STAGE_B + ARR_B);
        const __nv_bfloat16* sBh = (const __nv_bfloat16*)(smem + st * STAGE_B + 2 * ARR_B);
        const __nv_bfloat16* sBl = (const __nv_bfloat16*)(smem + st * STAGE_B + 3 * ARR_B);

#pragma unroll
        for (int kk = 0; kk < GBK; kk += 16) {
            uint32_t a[4][4], bfr[4][2];
            // load Ah fragments
#pragma unroll
            for (int im = 0; im < 4; im++) {
                int r = wm * 64 + im * 16 + g;
                a[im][0] = *(const uint32_t*)&sAh[(r    ) * GSTRIDE + kk + 2 * tig];
                a[im][1] = *(const uint32_t*)&sAh[(r + 8) * GSTRIDE + kk + 2 * tig];
                a[im][2] = *(const uint32_t*)&sAh[(r    ) * GSTRIDE + kk + 2 * tig + 8];
                a[im][3] = *(const uint32_t*)&sAh[(r + 8) * GSTRIDE + kk + 2 * tig + 8];
            }
            // Bh pass
#pragma unroll
            for (int in = 0; in < 4; in++) {
                int n0 = wn * 32 + in * 8 + g;
                bfr[in][0] = *(const uint32_t*)&sBh[n0 * GSTRIDE + kk + 2 * tig];
                bfr[in][1] = *(const uint32_t*)&sBh[n0 * GSTRIDE + kk + 2 * tig + 8];
            }
#pragma unroll
            for (int im = 0; im < 4; im++)
#pragma unroll
                for (int in = 0; in < 4; in++)
                    mma16816(acc[im][in], a[im], bfr[in]);
            // Bl pass (reuse Ah)
#pragma unroll
            for (int in = 0; in < 4; in++) {
                int n0 = wn * 32 + in * 8 + g;
                bfr[in][0] = *(const uint32_t*)&sBl[n0 * GSTRIDE + kk + 2 * tig];
                bfr[in][1] = *(const uint32_t*)&sBl[n0 * GSTRIDE + kk + 2 * tig + 8];
            }
#pragma unroll
            for (int im = 0; im < 4; im++)
#pragma unroll
                for (int in = 0; in < 4; in++)
                    mma16816(acc[im][in], a[im], bfr[in]);
            // Al x Bh pass
#pragma unroll
            for (int im = 0; im < 4; im++) {
                int r = wm * 64 + im * 16 + g;
                a[im][0] = *(const uint32_t*)&sAl[(r    ) * GSTRIDE + kk + 2 * tig];
                a[im][1] = *(const uint32_t*)&sAl[(r + 8) * GSTRIDE + kk + 2 * tig];
                a[im][2] = *(const uint32_t*)&sAl[(r    ) * GSTRIDE + kk + 2 * tig + 8];
                a[im][3] = *(const uint32_t*)&sAl[(r + 8) * GSTRIDE + kk + 2 * tig + 8];
            }
#pragma unroll
            for (int in = 0; in < 4; in++) {
                int n0 = wn * 32 + in * 8 + g;
                bfr[in][0] = *(const uint32_t*)&sBh[n0 * GSTRIDE + kk + 2 * tig];
                bfr[in][1] = *(const uint32_t*)&sBh[n0 * GSTRIDE + kk + 2 * tig + 8];
            }
#pragma unroll
            for (int im = 0; im < 4; im++)
#pragma unroll
                for (int in = 0; in < 4; in++)
                    mma16816(acc[im][in], a[im], bfr[in]);
        }
        __syncthreads();
    }

    // epilogue: acc -> C + bias
#pragma unroll
    for (int im = 0; im < 4; im++) {
        int r = bm + wm * 64 + im * 16 + g;
#pragma unroll
        for (int in = 0; in < 4; in++) {
            int ccol = bn + wn * 32 + in * 8 + 2 * tig;
            float2 b01 = *(const float2*)&bias[ccol];
            float2 o0 = make_float2(acc[im][in][0] + b01.x, acc[im][in][1] + b01.y);
            float2 o1 = make_float2(acc[im][in][2] + b01.x, acc[im][in][3] + b01.y);
            *(float2*)&C[(size_t)r * N + ccol]       = o0;
            *(float2*)&C[(size_t)(r + 8) * N + ccol] = o1;
        }
    }
}

// ---------------- Flash-style causal attention (fp32) ----------------
#define QT   64
#define KT   64
#define PADW 68

__global__ __launch_bounds__(256)
void attn_kernel(const int* __restrict__ mask, float* __restrict__ out)
{
    extern __shared__ float sm[];
    float* Qs = sm;
    float* Ks = Qs + 64 * PADW;
    float* Vs = Ks + 64 * PADW;
    float* Ps = Vs + 64 * PADW;

    const int tid = threadIdx.x;
    const int tx  = tid & 15;
    const int ty  = tid >> 4;
    const int qtile = blockIdx.x;
    const int bh    = blockIdx.y;
    const int b     = bh >> 4;
    const int h     = bh & 15;

    const int r0 = ty * 4;
    const int c0 = tx * 4;
    const float scale = 0.125f;
    const int qrow0 = qtile * QT;

    for (int i = tid; i < 64 * 16; i += 256) {
        int row  = i >> 4;
        int quad = i & 15;
        const float* src = &g_qkv[(size_t)(b * Ss + qrow0 + row) * E3 + h * HDs + quad * 4];
        float4 v = *(const float4*)src;
        Qs[(quad * 4 + 0) * PADW + row] = v.x;
        Qs[(quad * 4 + 1) * PADW + row] = v.y;
        Qs[(quad * 4 + 2) * PADW + row] = v.z;
        Qs[(quad * 4 + 3) * PADW + row] = v.w;
    }

    float m_i[4], l_i[4], o[4][4];
#pragma unroll
    for (int r = 0; r < 4; r++) {
        m_i[r] = -1e30f; l_i[r] = 0.0f;
#pragma unroll
        for (int c = 0; c < 4; c++) o[r][c] = 0.0f;
    }
    int g_r[4];
#pragma unroll
    for (int r = 0; r < 4; r++) g_r[r] = qrow0 + r0 + r;

    for (int j = 0; j <= qtile; j++) {
        __syncthreads();
        const int krow0 = j * KT;

        for (int i = tid; i < 64 * 16; i += 256) {
            int row  = i >> 4;
            int quad = i & 15;
            const float* kp = &g_qkv[(size_t)(b * Ss + krow0 + row) * E3 + Ee + h * HDs + quad * 4];
            float4 kv = *(const float4*)kp;
            Ks[(quad * 4 + 0) * PADW + row] = kv.x;
            Ks[(quad * 4 + 1) * PADW + row] = kv.y;
            Ks[(quad * 4 + 2) * PADW + row] = kv.z;
            Ks[(quad * 4 + 3) * PADW + row] = kv.w;
            float4 vv = *(const float4*)(kp + Ee);
            *(float4*)&Vs[row * PADW + quad * 4] = vv;
        }
        __syncthreads();

        float s[4][4];
#pragma unroll
        for (int r = 0; r < 4; r++)
#pragma unroll
            for (int c = 0; c < 4; c++) s[r][c] = 0.0f;

        for (int d = 0; d < 64; d++) {
            float4 q4 = *(const float4*)&Qs[d * PADW + r0];
            float4 k4 = *(const float4*)&Ks[d * PADW + c0];
            float qa[4] = {q4.x, q4.y, q4.z, q4.w};
            float ka[4] = {k4.x, k4.y, k4.z, k4.w};
#pragma unroll
            for (int r = 0; r < 4; r++)
#pragma unroll
                for (int c = 0; c < 4; c++) s[r][c] += qa[r] * ka[c];
        }

        float kvalid[4];
#pragma unroll
        for (int c = 0; c < 4; c++) {
            int gc = krow0 + c0 + c;
            kvalid[c] = (mask[b * Ss + gc] != 0) ? 1.0f : 0.0f;
        }
#pragma unroll
        for (int r = 0; r < 4; r++)
#pragma unroll
            for (int c = 0; c < 4; c++) {
                int gc = krow0 + c0 + c;
                bool ok = (gc <= g_r[r]) && (kvalid[c] > 0.5f);
                s[r][c] = ok ? s[r][c] * scale : -1e30f;
            }

        float mloc[4];
#pragma unroll
        for (int r = 0; r < 4; r++) {
            mloc[r] = fmaxf(fmaxf(s[r][0], s[r][1]), fmaxf(s[r][2], s[r][3]));
#pragma unroll
            for (int off = 8; off >= 1; off >>= 1)
                mloc[r] = fmaxf(mloc[r], __shfl_xor_sync(0xffffffffu, mloc[r], off));
        }

        float alpha[4];
#pragma unroll
        for (int r = 0; r < 4; r++) {
            float mn = fmaxf(m_i[r], mloc[r]);
            alpha[r] = __expf(m_i[r] - mn);
            m_i[r]   = mn;
        }

        float rowsum[4];
#pragma unroll
        for (int r = 0; r < 4; r++) {
            float rs = 0.0f;
#pragma unroll
            for (int c = 0; c < 4; c++) {
                float p = __expf(s[r][c] - m_i[r]);
                s[r][c] = p;
                rs += p;
            }
#pragma unroll
            for (int off = 8; off >= 1; off >>= 1)
                rs += __shfl_xor_sync(0xffffffffu, rs, off);
            rowsum[r] = rs;
        }

#pragma unroll
        for (int r = 0; r < 4; r++) {
            l_i[r] = l_i[r] * alpha[r] + rowsum[r];
#pragma unroll
            for (int c = 0; c < 4; c++) o[r][c] *= alpha[r];
        }

#pragma unroll
        for (int r = 0; r < 4; r++)
#pragma unroll
            for (int c = 0; c < 4; c++)
                Ps[(c0 + c) * PADW + (r0 + r)] = s[r][c];
        __syncthreads();

        for (int k = 0; k < 64; k++) {
            float4 p4 = *(const float4*)&Ps[k * PADW + r0];
            float4 v4 = *(const float4*)&Vs[k * PADW + c0];
            float pa[4] = {p4.x, p4.y, p4.z, p4.w};
            float va[4] = {v4.x, v4.y, v4.z, v4.w};
#pragma unroll
            for (int r = 0; r < 4; r++)
#pragma unroll
                for (int c = 0; c < 4; c++) o[r][c] += pa[r] * va[c];
        }
    }

#pragma unroll
    for (int r = 0; r < 4; r++) {
        float inv = 1.0f / l_i[r];
#pragma unroll
        for (int c = 0; c < 4; c++) {
            out[(size_t)(b * Ss + g_r[r]) * Ee + h * HDs + c0 + c] = o[r][c] * inv;
        }
    }
}

// ---------------- launch ----------------
extern "C" void kernel_launch(void* const* d_in, const int* in_sizes, int n_in,
                              void* d_out, int out_size)
{
    const float* X     = (const float*)d_in[0];
    const int*   mask  = (const int*)  d_in[1];
    const float* Wqkv  = (const float*)d_in[2];
    const float* bqkv  = (const float*)d_in[3];
    const float* Wproj = (const float*)d_in[4];
    const float* bproj = (const float*)d_in[5];
    float* out = (float*)d_out;

    float *qkv, *attn;
    __nv_bfloat16 *xhi, *xlo, *wqh, *wql, *wph, *wpl, *ahi, *alo;
    cudaGetSymbolAddress((void**)&qkv,  g_qkv);
    cudaGetSymbolAddress((void**)&attn, g_attn);
    cudaGetSymbolAddress((void**)&xhi,  g_xhi);
    cudaGetSymbolAddress((void**)&xlo,  g_xlo);
    cudaGetSymbolAddress((void**)&wqh,  g_wqh);
    cudaGetSymbolAddress((void**)&wql,  g_wql);
    cudaGetSymbolAddress((void**)&wph,  g_wph);
    cudaGetSymbolAddress((void**)&wpl,  g_wpl);
    cudaGetSymbolAddress((void**)&ahi,  g_ahi);
    cudaGetSymbolAddress((void**)&alo,  g_alo);

    cudaFuncSetAttribute(gemm_mma, cudaFuncAttributeMaxDynamicSharedMemorySize, GEMM_SMEM);

    // prep: split X, transpose+split weights
    split_hi_lo<<<(MTOT * Ee) / 4 / 256, 256>>>(X, xhi, xlo, MTOT * Ee);
    {
        dim3 blk(32, 8);
        transpose_split<<<dim3(E3 / 32, Kdim / 32), blk>>>(Wqkv, wqh, wql, Kdim, E3);
        transpose_split<<<dim3(Ee / 32, Kdim / 32), blk>>>(Wproj, wph, wpl, Kdim, Ee);
    }

    // 1) QKV = X @ Wqkv + b  (tensor cores)
    gemm_mma<<<dim3(E3 / 128, MTOT / 128), 256, GEMM_SMEM>>>(xhi, xlo, wqh, wql, bqkv, qkv, E3);

    // 2) causal attention (fp32)
    {
        const int smem = 4 * 64 * PADW * (int)sizeof(float);
        cudaFuncSetAttribute(attn_kernel, cudaFuncAttributeMaxDynamicSharedMemorySize, smem);
        attn_kernel<<<dim3(Ss / QT, Bb * Hh), 256, smem>>>(mask, attn);
    }

    // 3) out = attn @ Wproj + b  (tensor cores)
    split_hi_lo<<<(MTOT * Ee) / 4 / 256, 256>>>(attn, ahi, alo, MTOT * Ee);
    gemm_mma<<<dim3(Ee / 128, MTOT / 128), 256, GEMM_SMEM>>>(ahi, alo, wph, wpl, bproj, out, Ee);
}

// round 4
// speedup vs baseline: 2.1962x; 1.3242x over previous
#include <cuda_runtime.h>
#include <cuda_bf16.h>
#include <cstdint>
#include <math.h>

// ---------------- problem constants ----------------
#define Bb   4
#define Ss   1024
#define Ee   1024
#define Hh   16
#define HDs  64
#define MTOT 4096      // B*S
#define E3   3072      // 3*E
#define Kdim 1024

// ---------------- scratch (device globals) ----------------
__device__ float          g_qkv [MTOT * E3];     // [B*S, 3E] fp32
__device__ float          g_attn[MTOT * Ee];     // [B*S, E]  fp32
__device__ __nv_bfloat16  g_xhi [MTOT * Ee];     // X split; reused as Q_hi after QKV
__device__ __nv_bfloat16  g_xlo [MTOT * Ee];     //           reused as Q_lo
__device__ __nv_bfloat16  g_wqh [E3 * Ee];       // Wqkv^T
__device__ __nv_bfloat16  g_wql [E3 * Ee];
__device__ __nv_bfloat16  g_wph [Ee * Ee];       // Wproj^T
__device__ __nv_bfloat16  g_wpl [Ee * Ee];
__device__ __nv_bfloat16  g_ahi [MTOT * Ee];     // K_hi, then attn_hi for proj
__device__ __nv_bfloat16  g_alo [MTOT * Ee];     // K_lo, then attn_lo
__device__ __nv_bfloat16  g_vth [Bb * Ee * Ss];  // V^T split: [(b*E + h*64+d)*S + s]
__device__ __nv_bfloat16  g_vtl [Bb * Ee * Ss];

// ---------------- helpers ----------------
__device__ __forceinline__ void mma16816(float* c, const uint32_t* a, const uint32_t* b)
{
    asm volatile(
        "mma.sync.aligned.m16n8k16.row.col.f32.bf16.bf16.f32 "
        "{%0,%1,%2,%3}, {%4,%5,%6,%7}, {%8,%9}, {%0,%1,%2,%3};"
        : "+f"(c[0]), "+f"(c[1]), "+f"(c[2]), "+f"(c[3])
        : "r"(a[0]), "r"(a[1]), "r"(a[2]), "r"(a[3]), "r"(b[0]), "r"(b[1]));
}
__device__ __forceinline__ void cp16(uint32_t saddr, const void* g)
{
    asm volatile("cp.async.cg.shared.global [%0], [%1], 16;"
                 :: "r"(saddr), "l"(g));
}
__device__ __forceinline__ uint32_t smem_u32(const void* p) {
    uint32_t a;
    asm("{ .reg .u64 t; cvta.to.shared.u64 t, %1; cvt.u32.u64 %0, t; }"
        : "=r"(a) : "l"(p));
    return a;
}
// pack two floats into bf16x2 reg (lo = f0, hi = f1), plus residual pack
__device__ __forceinline__ void splitpack(float f0, float f1, uint32_t& hi, uint32_t& lo)
{
    __nv_bfloat16 h0 = __float2bfloat16_rn(f0);
    __nv_bfloat16 h1 = __float2bfloat16_rn(f1);
    __nv_bfloat162 hp = __halves2bfloat162(h0, h1);
    hi = *(uint32_t*)&hp;
    __nv_bfloat162 lp = __floats2bfloat162_rn(f0 - __bfloat162float(h0),
                                              f1 - __bfloat162float(h1));
    lo = *(uint32_t*)&lp;
}

// ---------------- split fp32 -> (bf16 hi, bf16 lo) ----------------
__global__ __launch_bounds__(256)
void split_hi_lo(const float* __restrict__ x,
                 __nv_bfloat16* __restrict__ hi,
                 __nv_bfloat16* __restrict__ lo, int n)
{
    int i = (blockIdx.x * 256 + threadIdx.x) * 4;
    if (i >= n) return;
    float4 v = *(const float4*)(x + i);
    __nv_bfloat16 h[4], l[4];
    float vv[4] = {v.x, v.y, v.z, v.w};
#pragma unroll
    for (int q = 0; q < 4; q++) {
        h[q] = __float2bfloat16_rn(vv[q]);
        l[q] = __float2bfloat16_rn(vv[q] - __bfloat162float(h[q]));
    }
    *(uint2*)(hi + i) = *(uint2*)h;
    *(uint2*)(lo + i) = *(uint2*)l;
}

// ---------------- split Q and K sections of qkv ----------------
__global__ __launch_bounds__(256)
void split_qk(const float* __restrict__ qkv,
              __nv_bfloat16* __restrict__ qh, __nv_bfloat16* __restrict__ ql,
              __nv_bfloat16* __restrict__ kh, __nv_bfloat16* __restrict__ kl)
{
    int t = blockIdx.x * 256 + threadIdx.x;
    int i4 = t * 4;
    if (i4 >= MTOT * Ee) return;
    int row = i4 >> 10, col = i4 & 1023;
    float4 q = *(const float4*)&qkv[(size_t)row * E3 + col];
    float4 k = *(const float4*)&qkv[(size_t)row * E3 + Ee + col];
    float qv[4] = {q.x, q.y, q.z, q.w}, kv[4] = {k.x, k.y, k.z, k.w};
    __nv_bfloat16 qhh[4], qll[4], khh[4], kll[4];
#pragma unroll
    for (int e = 0; e < 4; e++) {
        qhh[e] = __float2bfloat16_rn(qv[e]);
        qll[e] = __float2bfloat16_rn(qv[e] - __bfloat162float(qhh[e]));
        khh[e] = __float2bfloat16_rn(kv[e]);
        kll[e] = __float2bfloat16_rn(kv[e] - __bfloat162float(khh[e]));
    }
    *(uint2*)(qh + i4) = *(uint2*)qhh;
    *(uint2*)(ql + i4) = *(uint2*)qll;
    *(uint2*)(kh + i4) = *(uint2*)khh;
    *(uint2*)(kl + i4) = *(uint2*)kll;
}

// ---------------- transpose+split V: [s][hcol] -> [hcol][s] per batch ----------------
__global__ __launch_bounds__(256)
void transpose_v_split(const float* __restrict__ qkv,
                       __nv_bfloat16* __restrict__ vth, __nv_bfloat16* __restrict__ vtl)
{
    __shared__ float tile[32][33];
    int c0 = blockIdx.x * 32;     // hcol
    int s0 = blockIdx.y * 32;
    int b  = blockIdx.z;
    int tx = threadIdx.x, ty = threadIdx.y;   // 32 x 8
#pragma unroll
    for (int i = 0; i < 32; i += 8)
        tile[ty + i][tx] = qkv[(size_t)(b * Ss + s0 + ty + i) * E3 + 2 * Ee + c0 + tx];
    __syncthreads();
#pragma unroll
    for (int i = 0; i < 32; i += 8) {
        int ccol = c0 + ty + i, srow = s0 + tx;
        float v = tile[tx][ty + i];
        __nv_bfloat16 h = __float2bfloat16_rn(v);
        vth[(size_t)(b * Ee + ccol) * Ss + srow] = h;
        vtl[(size_t)(b * Ee + ccol) * Ss + srow] = __float2bfloat16_rn(v - __bfloat162float(h));
    }
}

// ---------------- transpose + split: W[K][N] -> T_hi/lo[N][K] ----------------
__global__ __launch_bounds__(256)
void transpose_split(const float* __restrict__ W,
                     __nv_bfloat16* __restrict__ Thi,
                     __nv_bfloat16* __restrict__ Tlo, int K, int N)
{
    __shared__ float tile[32][33];
    int n0 = blockIdx.x * 32, k0 = blockIdx.y * 32;
    int tx = threadIdx.x, ty = threadIdx.y;   // 32 x 8
#pragma unroll
    for (int i = 0; i < 32; i += 8)
        tile[ty + i][tx] = W[(size_t)(k0 + ty + i) * N + n0 + tx];
    __syncthreads();
#pragma unroll
    for (int i = 0; i < 32; i += 8) {
        int n = n0 + ty + i, k = k0 + tx;
        float v = tile[tx][ty + i];
        __nv_bfloat16 h = __float2bfloat16_rn(v);
        Thi[(size_t)n * K + k] = h;
        Tlo[(size_t)n * K + k] = __float2bfloat16_rn(v - __bfloat162float(h));
    }
}

// ---------------- split-bf16 tensor-core GEMM (unchanged from R3) ----------------
#define GBK      32
#define GSTRIDE  40
#define ARR_B    (128 * GSTRIDE * 2)
#define STAGE_B  (4 * ARR_B)
#define GEMM_SMEM (2 * STAGE_B)

__global__ __launch_bounds__(256, 1)
void gemm_mma(const __nv_bfloat16* __restrict__ Ahi, const __nv_bfloat16* __restrict__ Alo,
              const __nv_bfloat16* __restrict__ Bhi, const __nv_bfloat16* __restrict__ Blo,
              const float* __restrict__ bias, float* __restrict__ C, int N)
{
    extern __shared__ char smem[];
    const uint32_t sb = smem_u32(smem);
    const int tid  = threadIdx.x;
    const int wid  = tid >> 5, lane = tid & 31;
    const int wm   = wid >> 2, wn = wid & 3;
    const int g    = lane >> 2, tig = lane & 3;
    const int bm   = blockIdx.y * 128, bn = blockIdx.x * 128;
    const int NC   = Kdim / GBK;

    float acc[4][4][4];
#pragma unroll
    for (int im = 0; im < 4; im++)
#pragma unroll
        for (int in = 0; in < 4; in++)
#pragma unroll
            for (int q = 0; q < 4; q++) acc[im][in][q] = 0.0f;

    auto prefetch = [&](int c, int st) {
#pragma unroll
        for (int i = 0; i < 8; i++) {
            int idx = tid + i * 256;
            int arr = idx >> 9;
            int e   = idx & 511;
            int row = e >> 2;
            int seg = e & 3;
            const __nv_bfloat16* gp;
            size_t koff = (size_t)c * GBK + seg * 8;
            if      (arr == 0) gp = Ahi + (size_t)(bm + row) * Kdim + koff;
            else if (arr == 1) gp = Alo + (size_t)(bm + row) * Kdim + koff;
            else if (arr == 2) gp = Bhi + (size_t)(bn + row) * Kdim + koff;
            else               gp = Blo + (size_t)(bn + row) * Kdim + koff;
            uint32_t sa = sb + st * STAGE_B + arr * ARR_B + (row * GSTRIDE + seg * 8) * 2;
            cp16(sa, gp);
        }
        asm volatile("cp.async.commit_group;");
    };

    prefetch(0, 0);

    for (int c = 0; c < NC; c++) {
        const int st = c & 1;
        if (c + 1 < NC) {
            prefetch(c + 1, (c + 1) & 1);
            asm volatile("cp.async.wait_group 1;");
        } else {
            asm volatile("cp.async.wait_group 0;");
        }
        __syncthreads();

        const __nv_bfloat16* sAh = (const __nv_bfloat16*)(smem + st * STAGE_B);
        const __nv_bfloat16* sAl = (const __nv_bfloat16*)(smem + st * STAGE_B + ARR_B);
        const __nv_bfloat16* sBh = (const __nv_bfloat16*)(smem + st * STAGE_B + 2 * ARR_B);
        const __nv_bfloat16* sBl = (const __nv_bfloat16*)(smem + st * STAGE_B + 3 * ARR_B);

#pragma unroll
        for (int kk = 0; kk < GBK; kk += 16) {
            uint32_t a[4][4], bfr[4][2];
#pragma unroll
            for (int im = 0; im < 4; im++) {
                int r = wm * 64 + im * 16 + g;
                a[im][0] = *(const uint32_t*)&sAh[(r    ) * GSTRIDE + kk + 2 * tig];
                a[im][1] = *(const uint32_t*)&sAh[(r + 8) * GSTRIDE + kk + 2 * tig];
                a[im][2] = *(const uint32_t*)&sAh[(r    ) * GSTRIDE + kk + 2 * tig + 8];
                a[im][3] = *(const uint32_t*)&sAh[(r + 8) * GSTRIDE + kk + 2 * tig + 8];
            }
#pragma unroll
            for (int in = 0; in < 4; in++) {
                int n0 = wn * 32 + in * 8 + g;
                bfr[in][0] = *(const uint32_t*)&sBh[n0 * GSTRIDE + kk + 2 * tig];
                bfr[in][1] = *(const uint32_t*)&sBh[n0 * GSTRIDE + kk + 2 * tig + 8];
            }
#pragma unroll
            for (int im = 0; im < 4; im++)
#pragma unroll
                for (int in = 0; in < 4; in++)
                    mma16816(acc[im][in], a[im], bfr[in]);
#pragma unroll
            for (int in = 0; in < 4; in++) {
                int n0 = wn * 32 + in * 8 + g;
                bfr[in][0] = *(const uint32_t*)&sBl[n0 * GSTRIDE + kk + 2 * tig];
                bfr[in][1] = *(const uint32_t*)&sBl[n0 * GSTRIDE + kk + 2 * tig + 8];
            }
#pragma unroll
            for (int im = 0; im < 4; im++)
#pragma unroll
                for (int in = 0; in < 4; in++)
                    mma16816(acc[im][in], a[im], bfr[in]);
#pragma unroll
            for (int im = 0; im < 4; im++) {
                int r = wm * 64 + im * 16 + g;
                a[im][0] = *(const uint32_t*)&sAl[(r    ) * GSTRIDE + kk + 2 * tig];
                a[im][1] = *(const uint32_t*)&sAl[(r + 8) * GSTRIDE + kk + 2 * tig];
                a[im][2] = *(const uint32_t*)&sAl[(r    ) * GSTRIDE + kk + 2 * tig + 8];
                a[im][3] = *(const uint32_t*)&sAl[(r + 8) * GSTRIDE + kk + 2 * tig + 8];
            }
#pragma unroll
            for (int in = 0; in < 4; in++) {
                int n0 = wn * 32 + in * 8 + g;
                bfr[in][0] = *(const uint32_t*)&sBh[n0 * GSTRIDE + kk + 2 * tig];
                bfr[in][1] = *(const uint32_t*)&sBh[n0 * GSTRIDE + kk + 2 * tig + 8];
            }
#pragma unroll
            for (int im = 0; im < 4; im++)
#pragma unroll
                for (int in = 0; in < 4; in++)
                    mma16816(acc[im][in], a[im], bfr[in]);
        }
        __syncthreads();
    }

#pragma unroll
    for (int im = 0; im < 4; im++) {
        int r = bm + wm * 64 + im * 16 + g;
#pragma unroll
        for (int in = 0; in < 4; in++) {
            int ccol = bn + wn * 32 + in * 8 + 2 * tig;
            float2 b01 = *(const float2*)&bias[ccol];
            float2 o0 = make_float2(acc[im][in][0] + b01.x, acc[im][in][1] + b01.y);
            float2 o1 = make_float2(acc[im][in][2] + b01.x, acc[im][in][3] + b01.y);
            *(float2*)&C[(size_t)r * N + ccol]       = o0;
            *(float2*)&C[(size_t)(r + 8) * N + ccol] = o1;
        }
    }
}

// ---------------- tensor-core flash attention (split bf16) ----------------
// grid: (S/128, B*H); block 256 = 8 warps, warp wm owns 16 q rows.
#define VPAD 72

__global__ __launch_bounds__(256, 1)
void attn_mma(const __nv_bfloat16* __restrict__ qh, const __nv_bfloat16* __restrict__ ql,
              const __nv_bfloat16* __restrict__ kh, const __nv_bfloat16* __restrict__ kl,
              const __nv_bfloat16* __restrict__ vth, const __nv_bfloat16* __restrict__ vtl,
              const int* __restrict__ mask, float* __restrict__ out)
{
    __shared__ __nv_bfloat16 sKh[64][VPAD], sKl[64][VPAD];
    __shared__ __nv_bfloat16 sVh[64][VPAD], sVl[64][VPAD];   // Vt: [hd][kv]
    __shared__ int sMask[64];

    const int tid = threadIdx.x, wid = tid >> 5, lane = tid & 31;
    const int g = lane >> 2, tig = lane & 3;
    const int qt = blockIdx.x, bh = blockIdx.y;
    const int b = bh >> 4, h = bh & 15;
    const int q0 = qt * 128;
    const int wrow = q0 + wid * 16;
    const float scale = 0.125f;

    // Q fragments (resident): a[s][0..3] for ksteps s of hd
    uint32_t aqh[4][4], aql[4][4];
    {
        const __nv_bfloat16* qb = qh + (size_t)(b * Ss + wrow) * Ee + h * 64;
        const __nv_bfloat16* qbl = ql + (size_t)(b * Ss + wrow) * Ee + h * 64;
#pragma unroll
        for (int s = 0; s < 4; s++) {
            int k0 = s * 16 + 2 * tig;
            aqh[s][0] = *(const uint32_t*)&qb [(size_t)(g    ) * Ee + k0];
            aqh[s][1] = *(const uint32_t*)&qb [(size_t)(g + 8) * Ee + k0];
            aqh[s][2] = *(const uint32_t*)&qb [(size_t)(g    ) * Ee + k0 + 8];
            aqh[s][3] = *(const uint32_t*)&qb [(size_t)(g + 8) * Ee + k0 + 8];
            aql[s][0] = *(const uint32_t*)&qbl[(size_t)(g    ) * Ee + k0];
            aql[s][1] = *(const uint32_t*)&qbl[(size_t)(g + 8) * Ee + k0];
            aql[s][2] = *(const uint32_t*)&qbl[(size_t)(g    ) * Ee + k0 + 8];
            aql[s][3] = *(const uint32_t*)&qbl[(size_t)(g + 8) * Ee + k0 + 8];
        }
    }

    float m0 = -1e30f, m1 = -1e30f, l0 = 0.0f, l1 = 0.0f;
    float o[8][4];
#pragma unroll
    for (int t = 0; t < 8; t++)
#pragma unroll
        for (int e = 0; e < 4; e++) o[t][e] = 0.0f;

    const int row0 = wrow + g, row1 = wrow + 8 + g;
    const int ntiles = (qt + 1) * 2;

    for (int j = 0; j < ntiles; j++) {
        const int kv0 = j * 64;
        __syncthreads();
        // load K (hi/lo) [kv][hd] and Vt (hi/lo) [hd][kv]
        for (int i = tid; i < 512; i += 256) {
            int row = i >> 3, seg = (i & 7) * 8;
            *(uint4*)&sKh[row][seg] = *(const uint4*)&kh[(size_t)(b * Ss + kv0 + row) * Ee + h * 64 + seg];
            *(uint4*)&sKl[row][seg] = *(const uint4*)&kl[(size_t)(b * Ss + kv0 + row) * Ee + h * 64 + seg];
            *(uint4*)&sVh[row][seg] = *(const uint4*)&vth[(size_t)(b * Ee + h * 64 + row) * Ss + kv0 + seg];
            *(uint4*)&sVl[row][seg] = *(const uint4*)&vtl[(size_t)(b * Ee + h * 64 + row) * Ss + kv0 + seg];
        }
        if (tid < 64) sMask[tid] = mask[b * Ss + kv0 + tid];
        __syncthreads();

        // S = Q K^T (3-pass split)
        float c[8][4];
#pragma unroll
        for (int t = 0; t < 8; t++)
#pragma unroll
            for (int e = 0; e < 4; e++) c[t][e] = 0.0f;

#pragma unroll
        for (int s = 0; s < 4; s++) {
            int k0 = s * 16 + 2 * tig;
#pragma unroll
            for (int t = 0; t < 8; t++) {
                uint32_t bhf[2], blf[2];
                bhf[0] = *(const uint32_t*)&sKh[t * 8 + g][k0];
                bhf[1] = *(const uint32_t*)&sKh[t * 8 + g][k0 + 8];
                blf[0] = *(const uint32_t*)&sKl[t * 8 + g][k0];
                blf[1] = *(const uint32_t*)&sKl[t * 8 + g][k0 + 8];
                mma16816(c[t], aqh[s], bhf);
                mma16816(c[t], aqh[s], blf);
                mma16816(c[t], aql[s], bhf);
            }
        }

        // scale + causal + key mask
#pragma unroll
        for (int t = 0; t < 8; t++) {
            int lc0 = t * 8 + 2 * tig;
            int col0 = kv0 + lc0, col1 = col0 + 1;
            bool v0 = sMask[lc0] != 0, v1 = sMask[lc0 + 1] != 0;
            c[t][0] = (v0 && col0 <= row0) ? c[t][0] * scale : -1e30f;
            c[t][1] = (v1 && col1 <= row0) ? c[t][1] * scale : -1e30f;
            c[t][2] = (v0 && col0 <= row1) ? c[t][2] * scale : -1e30f;
            c[t][3] = (v1 && col1 <= row1) ? c[t][3] * scale : -1e30f;
        }

        // online softmax (rows g, g+8; stats across 4 tig lanes)
        float ml0 = -1e30f, ml1 = -1e30f;
#pragma unroll
        for (int t = 0; t < 8; t++) {
            ml0 = fmaxf(ml0, fmaxf(c[t][0], c[t][1]));
            ml1 = fmaxf(ml1, fmaxf(c[t][2], c[t][3]));
        }
        ml0 = fmaxf(ml0, __shfl_xor_sync(0xffffffffu, ml0, 1));
        ml0 = fmaxf(ml0, __shfl_xor_sync(0xffffffffu, ml0, 2));
        ml1 = fmaxf(ml1, __shfl_xor_sync(0xffffffffu, ml1, 1));
        ml1 = fmaxf(ml1, __shfl_xor_sync(0xffffffffu, ml1, 2));

        float mn0 = fmaxf(m0, ml0), mn1 = fmaxf(m1, ml1);
        float alpha0 = __expf(m0 - mn0), alpha1 = __expf(m1 - mn1);
        m0 = mn0; m1 = mn1;

        float rs0 = 0.0f, rs1 = 0.0f;
#pragma unroll
        for (int t = 0; t < 8; t++) {
            c[t][0] = __expf(c[t][0] - m0); rs0 += c[t][0];
            c[t][1] = __expf(c[t][1] - m0); rs0 += c[t][1];
            c[t][2] = __expf(c[t][2] - m1); rs1 += c[t][2];
            c[t][3] = __expf(c[t][3] - m1); rs1 += c[t][3];
        }
        rs0 += __shfl_xor_sync(0xffffffffu, rs0, 1);
        rs0 += __shfl_xor_sync(0xffffffffu, rs0, 2);
        rs1 += __shfl_xor_sync(0xffffffffu, rs1, 1);
        rs1 += __shfl_xor_sync(0xffffffffu, rs1, 2);

        l0 = l0 * alpha0 + rs0;
        l1 = l1 * alpha1 + rs1;
#pragma unroll
        for (int t = 0; t < 8; t++) {
            o[t][0] *= alpha0; o[t][1] *= alpha0;
            o[t][2] *= alpha1; o[t][3] *= alpha1;
        }

        // O += P @ V  (P fragments rebuilt from c in-place, split into hi/lo)
#pragma unroll
        for (int s = 0; s < 4; s++) {
            uint32_t aph[4], apl[4];
            splitpack(c[2 * s][0],     c[2 * s][1],     aph[0], apl[0]);
            splitpack(c[2 * s][2],     c[2 * s][3],     aph[1], apl[1]);
            splitpack(c[2 * s + 1][0], c[2 * s + 1][1], aph[2], apl[2]);
            splitpack(c[2 * s + 1][2], c[2 * s + 1][3], aph[3], apl[3]);
            int k0 = s * 16 + 2 * tig;
#pragma unroll
            for (int t = 0; t < 8; t++) {
                uint32_t bvh[2], bvl[2];
                bvh[0] = *(const uint32_t*)&sVh[t * 8 + g][k0];
                bvh[1] = *(const uint32_t*)&sVh[t * 8 + g][k0 + 8];
                bvl[0] = *(const uint32_t*)&sVl[t * 8 + g][k0];
                bvl[1] = *(const uint32_t*)&sVl[t * 8 + g][k0 + 8];
                mma16816(o[t], aph, bvh);
                mma16816(o[t], aph, bvl);
                mma16816(o[t], apl, bvh);
            }
        }
    }

    // epilogue
    float inv0 = 1.0f / l0, inv1 = 1.0f / l1;
    float* out0 = out + (size_t)(b * Ss + row0) * Ee + h * 64;
    float* out1 = out + (size_t)(b * Ss + row1) * Ee + h * 64;
#pragma unroll
    for (int t = 0; t < 8; t++) {
        int cc = t * 8 + 2 * tig;
        *(float2*)&out0[cc] = make_float2(o[t][0] * inv0, o[t][1] * inv0);
        *(float2*)&out1[cc] = make_float2(o[t][2] * inv1, o[t][3] * inv1);
    }
}

// ---------------- launch ----------------
extern "C" void kernel_launch(void* const* d_in, const int* in_sizes, int n_in,
                              void* d_out, int out_size)
{
    const float* X     = (const float*)d_in[0];
    const int*   mask  = (const int*)  d_in[1];
    const float* Wqkv  = (const float*)d_in[2];
    const float* bqkv  = (const float*)d_in[3];
    const float* Wproj = (const float*)d_in[4];
    const float* bproj = (const float*)d_in[5];
    float* out = (float*)d_out;

    float *qkv, *attn;
    __nv_bfloat16 *xhi, *xlo, *wqh, *wql, *wph, *wpl, *ahi, *alo, *vth, *vtl;
    cudaGetSymbolAddress((void**)&qkv,  g_qkv);
    cudaGetSymbolAddress((void**)&attn, g_attn);
    cudaGetSymbolAddress((void**)&xhi,  g_xhi);
    cudaGetSymbolAddress((void**)&xlo,  g_xlo);
    cudaGetSymbolAddress((void**)&wqh,  g_wqh);
    cudaGetSymbolAddress((void**)&wql,  g_wql);
    cudaGetSymbolAddress((void**)&wph,  g_wph);
    cudaGetSymbolAddress((void**)&wpl,  g_wpl);
    cudaGetSymbolAddress((void**)&ahi,  g_ahi);
    cudaGetSymbolAddress((void**)&alo,  g_alo);
    cudaGetSymbolAddress((void**)&vth,  g_vth);
    cudaGetSymbolAddress((void**)&vtl,  g_vtl);

    cudaFuncSetAttribute(gemm_mma, cudaFuncAttributeMaxDynamicSharedMemorySize, GEMM_SMEM);

    // prep: split X, transpose+split weights
    split_hi_lo<<<(MTOT * Ee) / 4 / 256, 256>>>(X, xhi, xlo, MTOT * Ee);
    {
        dim3 blk(32, 8);
        transpose_split<<<dim3(E3 / 32, Kdim / 32), blk>>>(Wqkv, wqh, wql, Kdim, E3);
        transpose_split<<<dim3(Ee / 32, Kdim / 32), blk>>>(Wproj, wph, wpl, Kdim, Ee);
    }

    // 1) QKV = X @ Wqkv + b  (tensor cores)
    gemm_mma<<<dim3(E3 / 128, MTOT / 128), 256, GEMM_SMEM>>>(xhi, xlo, wqh, wql, bqkv, qkv, E3);

    // 2) attention prep: split Q/K (reuse xhi/xlo as Q, ahi/alo as K), transpose+split V
    split_qk<<<(MTOT * Ee) / 4 / 256, 256>>>(qkv, xhi, xlo, ahi, alo);
    {
        dim3 blk(32, 8);
        transpose_v_split<<<dim3(Ee / 32, Ss / 32, Bb), blk>>>(qkv, vth, vtl);
    }

    // 3) tensor-core flash attention
    attn_mma<<<dim3(Ss / 128, Bb * Hh), 256>>>(xhi, xlo, ahi, alo, vth, vtl, mask, attn);

    // 4) out = attn @ Wproj + b  (tensor cores; reuse ahi/alo for attn split)
    split_hi_lo<<<(MTOT * Ee) / 4 / 256, 256>>>(attn, ahi, alo, MTOT * Ee);
    gemm_mma<<<dim3(Ee / 128, MTOT / 128), 256, GEMM_SMEM>>>(ahi, alo, wph, wpl, bproj, out, Ee);
}